// round 12
// baseline (speedup 1.0000x reference)
#include <cuda_runtime.h>
#include <cuda_fp16.h>
#include <cstdint>

#define B_   32
#define NA   512
#define NV   256
#define D_   384
#define BM   256
#define BN   256
#define BKE  64                     // fp16 elements per k-chunk (128 bytes/row)
#define NCH  (D_ / BKE)             // 6
#define NSTG 3
#define T_J  2                      // j-tiles per CTA

#define A_TILE   (BM * 128)         // 32768 B
#define B_TILE   (BN * 128)         // 32768 B
#define STAGE_B  (A_TILE + B_TILE)  // 65536 B
#define RING_B   (NSTG * STAGE_B)   // 196608 B
#define EPI_B    (4096 + 4096 + 64)
#define SMEM_BYTES (RING_B + EPI_B) // 204864 B

#define NTHREADS 512

// fp16 scratch (device globals: allocation-free)
__device__ __align__(16) __half g_audio_h[B_ * NA * D_];    // 12.6 MB
__device__ __align__(16) __half g_visual_h[B_ * NV * D_];   //  6.3 MB

// ---------------- helpers ----------------
__device__ __forceinline__ uint32_t smem_u32(const void* p) {
    uint32_t a;
    asm("{ .reg .u64 t; cvta.to.shared.u64 t, %1; cvt.u32.u64 %0, t; }" : "=r"(a) : "l"(p));
    return a;
}
#define CP_ASYNC16(dst, src) \
    asm volatile("cp.async.cg.shared.global [%0], [%1], 16;" :: "r"(dst), "l"(src) : "memory")
#define CP_COMMIT()  asm volatile("cp.async.commit_group;" ::: "memory")
#define CP_WAIT(N)   asm volatile("cp.async.wait_group %0;" :: "n"(N) : "memory")

#define LDSM_X4(r, addr) \
    asm volatile("ldmatrix.sync.aligned.m8n8.x4.shared.b16 {%0,%1,%2,%3}, [%4];" \
                 : "=r"((r)[0]), "=r"((r)[1]), "=r"((r)[2]), "=r"((r)[3]) : "r"(addr))

// fp16-accumulate MMA: D,C are 2 packed-half2 regs
__device__ __forceinline__ void mma_f16(uint32_t* d, const uint32_t* a, const uint32_t* b) {
    asm volatile(
        "mma.sync.aligned.m16n8k16.row.col.f16.f16.f16.f16 "
        "{%0,%1}, {%2,%3,%4,%5}, {%6,%7}, {%0,%1};"
        : "+r"(d[0]), "+r"(d[1])
        : "r"(a[0]), "r"(a[1]), "r"(a[2]), "r"(a[3]), "r"(b[0]), "r"(b[1]));
}

__device__ __forceinline__ void lse_comb(float& m, float& s, int o) {
    float om = __shfl_xor_sync(0xffffffffu, m, o);
    float os = __shfl_xor_sync(0xffffffffu, s, o);
    float mn = fmaxf(m, om);
    s = s * __expf((m - mn) * 0.5f) + os * __expf((om - mn) * 0.5f);
    m = mn;
}

// ---------------- fp32 -> fp16 conversion ----------------
__global__ void cvt_f16_kernel(const float* __restrict__ audio,
                               const float* __restrict__ visual) {
    const int NAE = B_ * NA * D_;
    const int NVE = B_ * NV * D_;
    int stride = gridDim.x * blockDim.x;
    for (int t = blockIdx.x * blockDim.x + threadIdx.x; t < NAE / 4; t += stride) {
        float4 v = reinterpret_cast<const float4*>(audio)[t];
        __half2 p0 = __floats2half2_rn(v.x, v.y);
        __half2 p1 = __floats2half2_rn(v.z, v.w);
        reinterpret_cast<uint2*>(g_audio_h)[t] =
            make_uint2(*reinterpret_cast<uint32_t*>(&p0), *reinterpret_cast<uint32_t*>(&p1));
    }
    for (int t = blockIdx.x * blockDim.x + threadIdx.x; t < NVE / 4; t += stride) {
        float4 v = reinterpret_cast<const float4*>(visual)[t];
        __half2 p0 = __floats2half2_rn(v.x, v.y);
        __half2 p1 = __floats2half2_rn(v.z, v.w);
        reinterpret_cast<uint2*>(g_visual_h)[t] =
            make_uint2(*reinterpret_cast<uint32_t*>(&p0), *reinterpret_cast<uint32_t*>(&p1));
    }
}

// ---------------- main fused kernel ----------------
__global__ void __launch_bounds__(NTHREADS, 1)
mm_f16_lse_kernel(float* __restrict__ out) {
    extern __shared__ char smem[];
    const uint32_t sb = smem_u32(smem);
    const int tid   = threadIdx.x;
    const int warp  = tid >> 5;
    const int lane  = tid & 31;
    const int warpm = warp >> 2;        // 0..3 -> 64-row strip
    const int warpn = warp & 3;         // 0..3 -> 64-col quarter
    const int g     = lane >> 2;        // 0..7
    const int c     = lane & 3;         // 0..3

    const int mt_b = blockIdx.x;        // 0..1
    const int jg   = blockIdx.y;        // 0..15 (j-group)
    const int i    = blockIdx.z;        // audio batch

    const __half* Ab = g_audio_h + ((size_t)i * NA + (size_t)mt_b * BM) * D_;

    uint32_t acc[4][8][2];              // packed half2: [mt][nt][row-half]
    #pragma unroll
    for (int mt = 0; mt < 4; mt++)
        #pragma unroll
        for (int nt = 0; nt < 8; nt++) { acc[mt][nt][0] = 0u; acc[mt][nt][1] = 0u; }

    // ---- full-stage loader (prologue only) ----
    auto load_stage = [&](int s, const __half* Vb, int kb) {
        const uint32_t a_off = s * STAGE_B;
        const uint32_t b_off = a_off + A_TILE;
        #pragma unroll
        for (int e = 0; e < 4; e++) {             // A: 256 rows x 8 x 16B
            int idx = e * NTHREADS + tid;
            int row = idx >> 3, gg = idx & 7;
            uint32_t loc = row * 128 + ((gg * 16) ^ ((row & 7) << 4));
            CP_ASYNC16(sb + a_off + loc, Ab + (size_t)row * D_ + kb + gg * 8);
        }
        #pragma unroll
        for (int e = 0; e < 4; e++) {             // B: 256 rows x 8 x 16B
            int idx = e * NTHREADS + tid;
            int row = idx >> 3, gg = idx & 7;
            uint32_t loc = row * 128 + ((gg * 16) ^ ((row & 7) << 4));
            CP_ASYNC16(sb + b_off + loc, Vb + (size_t)row * D_ + kb + gg * 8);
        }
        CP_COMMIT();
    };

    // ---- per-lane ldmatrix address components ----
    const uint32_t a_row  = (uint32_t)(warpm * 64 + (lane & 15));
    const uint32_t a_cxtr = ((lane >> 4) & 1) * 16;
    const uint32_t b_row  = (uint32_t)(warpn * 64 + ((lane & 7) | ((lane & 16) >> 1)));
    const uint32_t b_cxtr = ((lane >> 3) & 1) * 16;
    const uint32_t swx    = (uint32_t)((lane & 7) << 4);

    // compute chunk in stage s; interleave loads of chunk (stage s2) from Ab/Vb2 @kb2
    auto compute = [&](int s, int s2, const __half* Vb2, int kb2, bool dl) {
        const uint32_t a_base = sb + s * STAGE_B + a_row * 128;
        const uint32_t b_base = sb + s * STAGE_B + A_TILE + b_row * 128;
        const uint32_t a2_off = s2 * STAGE_B;
        const uint32_t b2_off = a2_off + A_TILE;
        #pragma unroll
        for (int ks = 0; ks < 4; ks++) {          // 4 x k16 per 64-wide chunk
            const uint32_t acol = (uint32_t)(ks * 32 + a_cxtr) ^ swx;
            const uint32_t bcol = (uint32_t)(ks * 32 + b_cxtr) ^ swx;
            uint32_t af[4][4], bf[4][4];
            #pragma unroll
            for (int mt = 0; mt < 4; mt++)
                LDSM_X4(af[mt], a_base + mt * (16 * 128) + acol);
            #pragma unroll
            for (int p = 0; p < 4; p++)
                LDSM_X4(bf[p], b_base + p * (16 * 128) + bcol);
            // interleaved next-chunk loads: 2 granule batches per ks (A first, then B)
            if (dl) {
                #pragma unroll
                for (int e2 = 0; e2 < 2; e2++) {
                    const int batch = ks * 2 + e2;          // 0..7
                    int idx = (batch & 3) * NTHREADS + tid;
                    int row = idx >> 3, gg = idx & 7;
                    uint32_t loc = row * 128 + ((gg * 16) ^ ((row & 7) << 4));
                    if (batch < 4)
                        CP_ASYNC16(sb + a2_off + loc, Ab + (size_t)row * D_ + kb2 + gg * 8);
                    else
                        CP_ASYNC16(sb + b2_off + loc, Vb2 + (size_t)row * D_ + kb2 + gg * 8);
                }
            }
            #pragma unroll
            for (int mt = 0; mt < 4; mt++)
                #pragma unroll
                for (int p = 0; p < 4; p++) {
                    mma_f16(acc[mt][2 * p],     af[mt], &bf[p][0]);
                    mma_f16(acc[mt][2 * p + 1], af[mt], &bf[p][2]);
                }
        }
        CP_COMMIT();   // exactly one group per chunk (possibly empty)
    };

    // ---- epilogue reduction region (never collides with ring stages) ----
    float* pmax = reinterpret_cast<float*>(smem + RING_B);          // [256][4]
    float* psum = reinterpret_cast<float*>(smem + RING_B + 4096);   // [256][4]
    float* wsum = reinterpret_cast<float*>(smem + RING_B + 8192);   // [8]

    // ---- prologue: first 3 chunks of tile 0 ----
    {
        const __half* Vb0 = g_visual_h + (size_t)(jg * T_J) * NV * D_;
        load_stage(0, Vb0, 0 * BKE);
        load_stage(1, Vb0, 1 * BKE);
        load_stage(2, Vb0, 2 * BKE);
    }

    for (int t = 0; t < T_J; t++) {
        #pragma unroll
        for (int kc = 0; kc < NCH; kc++) {
            CP_WAIT(1);
            __syncthreads();
            // lookahead chunk gc+2
            const int kc2 = (kc + 2) % NCH;            // compile-time per kc
            const int tadd = (kc + 2) / NCH;           // 0 or 1
            const bool dl = (t + tadd) < T_J && !(t == T_J - 1 && kc >= NCH - 2);
            const __half* Vb2 = g_visual_h + (size_t)(jg * T_J + t + tadd) * NV * D_;
            compute(kc % NSTG, kc2 % NSTG, Vb2, kc2 * BKE, dl);
        }

        // ---- per-tile epilogue: tau*logsumexp over 256 cols, mean over rows ----
        #pragma unroll
        for (int mt = 0; mt < 4; mt++) {
            int r0 = warpm * 64 + mt * 16 + g;
            float v0[16], v1[16];
            #pragma unroll
            for (int nt = 0; nt < 8; nt++) {
                float2 x0 = __half22float2(*reinterpret_cast<__half2*>(&acc[mt][nt][0]));
                float2 x1 = __half22float2(*reinterpret_cast<__half2*>(&acc[mt][nt][1]));
                v0[2 * nt] = x0.x; v0[2 * nt + 1] = x0.y;
                v1[2 * nt] = x1.x; v1[2 * nt + 1] = x1.y;
            }
            float m0 = v0[0], m1 = v1[0];
            #pragma unroll
            for (int e = 1; e < 16; e++) { m0 = fmaxf(m0, v0[e]); m1 = fmaxf(m1, v1[e]); }
            float s0 = 0.f, s1 = 0.f;
            #pragma unroll
            for (int e = 0; e < 16; e++) {
                s0 += __expf((v0[e] - m0) * 0.5f);
                s1 += __expf((v1[e] - m1) * 0.5f);
            }
            lse_comb(m0, s0, 1); lse_comb(m0, s0, 2);
            lse_comb(m1, s1, 1); lse_comb(m1, s1, 2);
            if (c == 0) {
                pmax[(r0)     * 4 + warpn] = m0;  psum[(r0)     * 4 + warpn] = s0;
                pmax[(r0 + 8) * 4 + warpn] = m1;  psum[(r0 + 8) * 4 + warpn] = s1;
            }
        }
        __syncthreads();

        if (tid < 256) {
            float m = pmax[tid * 4];
            #pragma unroll
            for (int w = 1; w < 4; w++) m = fmaxf(m, pmax[tid * 4 + w]);
            float s = 0.f;
            #pragma unroll
            for (int w = 0; w < 4; w++)
                s += psum[tid * 4 + w] * __expf((pmax[tid * 4 + w] - m) * 0.5f);
            float lse = m + 2.0f * __logf(s);
            #pragma unroll
            for (int o = 16; o > 0; o >>= 1) lse += __shfl_xor_sync(0xffffffffu, lse, o);
            if (lane == 0) wsum[warp] = lse;
        }
        __syncthreads();
        if (tid == 0) {
            float tsum = 0.f;
            #pragma unroll
            for (int w = 0; w < 8; w++) tsum += wsum[w];
            atomicAdd(&out[i * B_ + (jg * T_J + t)], tsum * (1.0f / NA));
        }

        // reset accumulators for next tile
        #pragma unroll
        for (int mt = 0; mt < 4; mt++)
            #pragma unroll
            for (int nt = 0; nt < 8; nt++) { acc[mt][nt][0] = 0u; acc[mt][nt][1] = 0u; }
    }
}

// ---------------- launch ----------------
extern "C" void kernel_launch(void* const* d_in, const int* in_sizes, int n_in,
                              void* d_out, int out_size) {
    const float* audio  = (const float*)d_in[0];   // (32, 512, 384) fp32
    const float* visual = (const float*)d_in[1];   // (32, 256, 384) fp32
    float* out = (float*)d_out;                    // (32, 32) fp32

    cudaFuncSetAttribute(mm_f16_lse_kernel,
                         cudaFuncAttributeMaxDynamicSharedMemorySize, SMEM_BYTES);

    cudaMemsetAsync(out, 0, (size_t)out_size * sizeof(float));
    cvt_f16_kernel<<<1184, 256>>>(audio, visual);

    dim3 grid(NA / BM, B_ / T_J, B_);   // (2, 16, 32)
    mm_f16_lse_kernel<<<grid, NTHREADS, SMEM_BYTES>>>(out);
}

// round 13
// speedup vs baseline: 1.6245x; 1.6245x over previous
#include <cuda_runtime.h>
#include <cuda_fp16.h>
#include <cstdint>

#define B_   32
#define NA   512
#define NV   256
#define D_   384
#define BM   128
#define BN   256
#define BKE  64                     // fp16 elements per k-chunk (128 bytes/row)
#define NCH  (D_ / BKE)             // 6
#define NSTG 2

#define A_TILE   (BM * 128)         // 16384 B
#define B_TILE   (BN * 128)         // 32768 B
#define STAGE_B  (A_TILE + B_TILE)  // 49152 B
#define SMEM_BYTES (NSTG * STAGE_B) // 98304 B -> 2 CTAs/SM

#define NTHREADS 256

// fp16 scratch (device globals: allocation-free)
__device__ __align__(16) __half g_audio_h[B_ * NA * D_];    // 12.6 MB
__device__ __align__(16) __half g_visual_h[B_ * NV * D_];   //  6.3 MB

// ---------------- helpers ----------------
__device__ __forceinline__ uint32_t smem_u32(const void* p) {
    uint32_t a;
    asm("{ .reg .u64 t; cvta.to.shared.u64 t, %1; cvt.u32.u64 %0, t; }" : "=r"(a) : "l"(p));
    return a;
}
#define CP_ASYNC16(dst, src) \
    asm volatile("cp.async.cg.shared.global [%0], [%1], 16;" :: "r"(dst), "l"(src) : "memory")
#define CP_COMMIT()  asm volatile("cp.async.commit_group;" ::: "memory")
#define CP_WAIT(N)   asm volatile("cp.async.wait_group %0;" :: "n"(N) : "memory")

#define LDSM_X4(r, addr) \
    asm volatile("ldmatrix.sync.aligned.m8n8.x4.shared.b16 {%0,%1,%2,%3}, [%4];" \
                 : "=r"((r)[0]), "=r"((r)[1]), "=r"((r)[2]), "=r"((r)[3]) : "r"(addr))

// fp16-accumulate MMA: D,C are 2 packed-half2 regs
__device__ __forceinline__ void mma_f16(uint32_t* d, const uint32_t* a, const uint32_t* b) {
    asm volatile(
        "mma.sync.aligned.m16n8k16.row.col.f16.f16.f16.f16 "
        "{%0,%1}, {%2,%3,%4,%5}, {%6,%7}, {%0,%1};"
        : "+r"(d[0]), "+r"(d[1])
        : "r"(a[0]), "r"(a[1]), "r"(a[2]), "r"(a[3]), "r"(b[0]), "r"(b[1]));
}

__device__ __forceinline__ void lse_comb(float& m, float& s, int o) {
    float om = __shfl_xor_sync(0xffffffffu, m, o);
    float os = __shfl_xor_sync(0xffffffffu, s, o);
    float mn = fmaxf(m, om);
    s = s * __expf((m - mn) * 0.5f) + os * __expf((om - mn) * 0.5f);
    m = mn;
}

// ---------------- fp32 -> fp16 conversion ----------------
__global__ void cvt_f16_kernel(const float* __restrict__ audio,
                               const float* __restrict__ visual) {
    const int NAE = B_ * NA * D_;
    const int NVE = B_ * NV * D_;
    int stride = gridDim.x * blockDim.x;
    for (int t = blockIdx.x * blockDim.x + threadIdx.x; t < NAE / 4; t += stride) {
        float4 v = reinterpret_cast<const float4*>(audio)[t];
        __half2 p0 = __floats2half2_rn(v.x, v.y);
        __half2 p1 = __floats2half2_rn(v.z, v.w);
        reinterpret_cast<uint2*>(g_audio_h)[t] =
            make_uint2(*reinterpret_cast<uint32_t*>(&p0), *reinterpret_cast<uint32_t*>(&p1));
    }
    for (int t = blockIdx.x * blockDim.x + threadIdx.x; t < NVE / 4; t += stride) {
        float4 v = reinterpret_cast<const float4*>(visual)[t];
        __half2 p0 = __floats2half2_rn(v.x, v.y);
        __half2 p1 = __floats2half2_rn(v.z, v.w);
        reinterpret_cast<uint2*>(g_visual_h)[t] =
            make_uint2(*reinterpret_cast<uint32_t*>(&p0), *reinterpret_cast<uint32_t*>(&p1));
    }
}

// ---------------- main fused kernel ----------------
__global__ void __launch_bounds__(NTHREADS, 2)
mm_f16_lse_kernel(float* __restrict__ out) {
    extern __shared__ char smem[];
    const uint32_t sb = smem_u32(smem);
    const int tid   = threadIdx.x;
    const int warp  = tid >> 5;
    const int lane  = tid & 31;
    const int warpm = warp >> 2;        // 0..1 -> 64-row strip
    const int warpn = warp & 3;         // 0..3 -> 64-col quarter
    const int g     = lane >> 2;        // 0..7
    const int c     = lane & 3;         // 0..3

    const int mt_b = blockIdx.x;        // 0..3
    const int j    = blockIdx.y;        // visual batch
    const int i    = blockIdx.z;        // audio batch

    const __half* Ab = g_audio_h  + ((size_t)i * NA + (size_t)mt_b * BM) * D_;
    const __half* Vb = g_visual_h + (size_t)j * NV * D_;

    uint32_t acc[4][8][2];              // packed half2: [mt][nt][row-half]
    #pragma unroll
    for (int mt = 0; mt < 4; mt++)
        #pragma unroll
        for (int nt = 0; nt < 8; nt++) { acc[mt][nt][0] = 0u; acc[mt][nt][1] = 0u; }

    // ---- stage loader: SW128-swizzled smem, cp.async 16B ----
    auto load_stage = [&](int s, int kc) {
        const uint32_t a_off = s * STAGE_B;
        const uint32_t b_off = a_off + A_TILE;
        const int kb = kc * BKE;
        #pragma unroll
        for (int e = 0; e < 4; e++) {             // A: 128 rows x 8 x 16B = 1024
            int idx = e * NTHREADS + tid;
            int row = idx >> 3, gg = idx & 7;
            uint32_t loc = row * 128 + ((gg * 16) ^ ((row & 7) << 4));
            CP_ASYNC16(sb + a_off + loc, Ab + (size_t)row * D_ + kb + gg * 8);
        }
        #pragma unroll
        for (int e = 0; e < 8; e++) {             // B: 256 rows x 8 x 16B = 2048
            int idx = e * NTHREADS + tid;
            int row = idx >> 3, gg = idx & 7;
            uint32_t loc = row * 128 + ((gg * 16) ^ ((row & 7) << 4));
            CP_ASYNC16(sb + b_off + loc, Vb + (size_t)row * D_ + kb + gg * 8);
        }
        CP_COMMIT();
    };

    // ---- per-lane ldmatrix address components ----
    const uint32_t a_row  = (uint32_t)(warpm * 64 + (lane & 15));
    const uint32_t a_cxtr = ((lane >> 4) & 1) * 16;
    const uint32_t b_row  = (uint32_t)(warpn * 64 + ((lane & 7) | ((lane & 16) >> 1)));
    const uint32_t b_cxtr = ((lane >> 3) & 1) * 16;
    const uint32_t swx    = (uint32_t)((lane & 7) << 4);

    auto compute = [&](int s) {
        const uint32_t a_base = sb + s * STAGE_B + a_row * 128;
        const uint32_t b_base = sb + s * STAGE_B + A_TILE + b_row * 128;
        #pragma unroll
        for (int ks = 0; ks < 4; ks++) {          // 4 x k16 per 64-wide chunk
            const uint32_t acol = (uint32_t)(ks * 32 + a_cxtr) ^ swx;
            const uint32_t bcol = (uint32_t)(ks * 32 + b_cxtr) ^ swx;
            uint32_t af[4][4], bf[4][4];
            #pragma unroll
            for (int mt = 0; mt < 4; mt++)
                LDSM_X4(af[mt], a_base + mt * (16 * 128) + acol);
            #pragma unroll
            for (int p = 0; p < 4; p++)
                LDSM_X4(bf[p], b_base + p * (16 * 128) + bcol);
            #pragma unroll
            for (int mt = 0; mt < 4; mt++)
                #pragma unroll
                for (int p = 0; p < 4; p++) {
                    mma_f16(acc[mt][2 * p],     af[mt], &bf[p][0]);
                    mma_f16(acc[mt][2 * p + 1], af[mt], &bf[p][2]);
                }
        }
    };

    // ---- 2-stage pipelined mainloop ----
    load_stage(0, 0);
    load_stage(1, 1);
    #pragma unroll
    for (int kc = 0; kc < NCH; kc++) {
        if (kc < NCH - 1) { CP_WAIT(1); } else { CP_WAIT(0); }
        __syncthreads();
        compute(kc & 1);
        __syncthreads();
        if (kc + 2 < NCH) load_stage(kc & 1, kc + 2);
    }

    // ---- epilogue: tau*logsumexp over 256 cols, mean over rows ----
    float* pmax = reinterpret_cast<float*>(smem);          // [128][4]
    float* psum = pmax + 512;                              // [128][4]
    float* wsum = pmax + 1024;                             // [4]

    #pragma unroll
    for (int mt = 0; mt < 4; mt++) {
        int r0 = warpm * 64 + mt * 16 + g;
        float v0[16], v1[16];
        #pragma unroll
        for (int nt = 0; nt < 8; nt++) {
            float2 x0 = __half22float2(*reinterpret_cast<__half2*>(&acc[mt][nt][0]));
            float2 x1 = __half22float2(*reinterpret_cast<__half2*>(&acc[mt][nt][1]));
            v0[2 * nt] = x0.x; v0[2 * nt + 1] = x0.y;
            v1[2 * nt] = x1.x; v1[2 * nt + 1] = x1.y;
        }
        float m0 = v0[0], m1 = v1[0];
        #pragma unroll
        for (int e = 1; e < 16; e++) { m0 = fmaxf(m0, v0[e]); m1 = fmaxf(m1, v1[e]); }
        float s0 = 0.f, s1 = 0.f;
        #pragma unroll
        for (int e = 0; e < 16; e++) {
            s0 += __expf((v0[e] - m0) * 0.5f);
            s1 += __expf((v1[e] - m1) * 0.5f);
        }
        lse_comb(m0, s0, 1); lse_comb(m0, s0, 2);
        lse_comb(m1, s1, 1); lse_comb(m1, s1, 2);
        if (c == 0) {
            pmax[(r0)     * 4 + warpn] = m0;  psum[(r0)     * 4 + warpn] = s0;
            pmax[(r0 + 8) * 4 + warpn] = m1;  psum[(r0 + 8) * 4 + warpn] = s1;
        }
    }
    __syncthreads();

    if (tid < 128) {
        float m = pmax[tid * 4];
        #pragma unroll
        for (int w = 1; w < 4; w++) m = fmaxf(m, pmax[tid * 4 + w]);
        float s = 0.f;
        #pragma unroll
        for (int w = 0; w < 4; w++) s += psum[tid * 4 + w] * __expf((pmax[tid * 4 + w] - m) * 0.5f);
        float lse = m + 2.0f * __logf(s);
        #pragma unroll
        for (int o = 16; o > 0; o >>= 1) lse += __shfl_xor_sync(0xffffffffu, lse, o);
        if (lane == 0) wsum[warp] = lse;
    }
    __syncthreads();
    if (tid == 0) {
        float t = wsum[0] + wsum[1] + wsum[2] + wsum[3];
        atomicAdd(&out[i * B_ + j], t * (1.0f / NA));
    }
}

// ---------------- launch ----------------
extern "C" void kernel_launch(void* const* d_in, const int* in_sizes, int n_in,
                              void* d_out, int out_size) {
    const float* audio  = (const float*)d_in[0];   // (32, 512, 384) fp32
    const float* visual = (const float*)d_in[1];   // (32, 256, 384) fp32
    float* out = (float*)d_out;                    // (32, 32) fp32

    cudaFuncSetAttribute(mm_f16_lse_kernel,
                         cudaFuncAttributeMaxDynamicSharedMemorySize, SMEM_BYTES);

    cudaMemsetAsync(out, 0, (size_t)out_size * sizeof(float));
    cvt_f16_kernel<<<1184, 256>>>(audio, visual);

    dim3 grid(NA / BM, B_, B_);   // (4, 32, 32)
    mm_f16_lse_kernel<<<grid, NTHREADS, SMEM_BYTES>>>(out);
}